// round 12
// baseline (speedup 1.0000x reference)
#include <cuda_runtime.h>
#include <cuda_fp16.h>
#include <math.h>
#include <stdint.h>

#define BN 4
#define SS 4096
#define CC 256
#define M_TOT (BN*SS)

__device__ float  g_xn  [(size_t)BN*SS*CC];
__device__ __half g_xn16[(size_t)BN*SS*CC];
__device__ __half g_ct16[(size_t)BN*SS*CC];
__device__ __half g_q16 [(size_t)BN*SS*CC];
__device__ __half g_k16 [(size_t)BN*SS*CC];
__device__ __half g_v16 [(size_t)BN*SS*CC];
__device__ __half g_o16 [(size_t)BN*SS*CC];
__device__ __half g_wq16[CC*CC];
__device__ __half g_wk16[CC*CC];
__device__ __half g_wv16[CC*CC];
__device__ __half g_wp16[CC*CC];

__device__ __forceinline__ uint32_t smem_u32(const void* p){
    uint32_t a; asm("{ .reg .u64 t; cvta.to.shared.u64 t, %1; cvt.u32.u64 %0, t; }":"=r"(a):"l"(p)); return a;
}
#define MMAH(d,a0,a1,a2,a3,b0,b1) \
    asm("mma.sync.aligned.m16n8k16.row.col.f32.f16.f16.f32 {%0,%1,%2,%3},{%4,%5,%6,%7},{%8,%9},{%0,%1,%2,%3};" \
        :"+f"(d[0]),"+f"(d[1]),"+f"(d[2]),"+f"(d[3]) \
        :"r"(a0),"r"(a1),"r"(a2),"r"(a3),"r"(b0),"r"(b1))
#define LDSM4(r0,r1,r2,r3,a) asm volatile("ldmatrix.sync.aligned.m8n8.x4.shared.b16 {%0,%1,%2,%3},[%4];" \
        :"=r"(r0),"=r"(r1),"=r"(r2),"=r"(r3):"r"(a))
#define LDSM4T(r0,r1,r2,r3,a) asm volatile("ldmatrix.sync.aligned.m8n8.x4.trans.shared.b16 {%0,%1,%2,%3},[%4];" \
        :"=r"(r0),"=r"(r1),"=r"(r2),"=r"(r3):"r"(a))
#define CPAH(off_h, src) asm volatile("cp.async.cg.shared.global [%0], [%1], 16;"::"r"(smb+(uint32_t)((off_h)*2)),"l"(src):"memory")
#define CPC()  asm volatile("cp.async.commit_group;":::"memory")
#define CPW0() asm volatile("cp.async.wait_group 0;":::"memory")
__device__ __forceinline__ uint32_t h2u(__half2 x){ return *(uint32_t*)&x; }

// ---------------- LayerNorm ----------------
__global__ void ln_kernel(const float* __restrict__ x, const float* __restrict__ gamma,
                          const float* __restrict__ beta, float* __restrict__ out32,
                          __half* __restrict__ out16){
    int wid = threadIdx.x>>5, lane = threadIdx.x&31;
    size_t row = (size_t)blockIdx.x*8 + wid;
    const float* xr = x + row*CC + lane*8;
    float4 v0 = *(const float4*)xr, v1 = *(const float4*)(xr+4);
    float s = v0.x+v0.y+v0.z+v0.w+v1.x+v1.y+v1.z+v1.w;
    #pragma unroll
    for(int o=16;o;o>>=1) s += __shfl_xor_sync(~0u,s,o);
    float mu = s*(1.f/CC);
    v0.x-=mu;v0.y-=mu;v0.z-=mu;v0.w-=mu;v1.x-=mu;v1.y-=mu;v1.z-=mu;v1.w-=mu;
    float q = v0.x*v0.x+v0.y*v0.y+v0.z*v0.z+v0.w*v0.w+v1.x*v1.x+v1.y*v1.y+v1.z*v1.z+v1.w*v1.w;
    #pragma unroll
    for(int o=16;o;o>>=1) q += __shfl_xor_sync(~0u,q,o);
    float rs = rsqrtf(q*(1.f/CC)+1e-3f);
    const float4 ga0 = *(const float4*)(gamma+lane*8), ga1 = *(const float4*)(gamma+lane*8+4);
    const float4 be0 = *(const float4*)(beta +lane*8), be1 = *(const float4*)(beta +lane*8+4);
    float4 o0,o1;
    o0.x=v0.x*rs*ga0.x+be0.x; o0.y=v0.y*rs*ga0.y+be0.y; o0.z=v0.z*rs*ga0.z+be0.z; o0.w=v0.w*rs*ga0.w+be0.w;
    o1.x=v1.x*rs*ga1.x+be1.x; o1.y=v1.y*rs*ga1.y+be1.y; o1.z=v1.z*rs*ga1.z+be1.z; o1.w=v1.w*rs*ga1.w+be1.w;
    float* op = out32 + row*CC + lane*8;
    *(float4*)op = o0; *(float4*)(op+4) = o1;
    uint4 hp = make_uint4(h2u(__floats2half2_rn(o0.x,o0.y)), h2u(__floats2half2_rn(o0.z,o0.w)),
                          h2u(__floats2half2_rn(o1.x,o1.y)), h2u(__floats2half2_rn(o1.z,o1.w)));
    *(uint4*)(out16 + row*CC + lane*8) = hp;
}

// ---------------- fused fp32->fp16 convert ----------------
__global__ void cvt_all(const float* __restrict__ ctx, __half* __restrict__ dctx,
        const float* __restrict__ Wq, const float* __restrict__ Wk,
        const float* __restrict__ Wv, const float* __restrict__ Wp,
        __half* __restrict__ dwq, __half* __restrict__ dwk,
        __half* __restrict__ dwv, __half* __restrict__ dwp){
    int blk = blockIdx.x;
    const float* src; __half* dst; size_t base;
    if(blk < 2048){ src=ctx; dst=dctx; base=(size_t)blk*2048; }
    else{
        int w=(blk-2048)>>5, off=(blk-2048)&31;
        src = w==0?Wq : w==1?Wk : w==2?Wv : Wp;
        dst = w==0?dwq: w==1?dwk: w==2?dwv: dwp;
        base = (size_t)off*2048;
    }
    size_t i = base + (size_t)threadIdx.x*8;
    float4 a=*(const float4*)(src+i), b=*(const float4*)(src+i+4);
    uint4 r = make_uint4(h2u(__floats2half2_rn(a.x,a.y)),h2u(__floats2half2_rn(a.z,a.w)),
                         h2u(__floats2half2_rn(b.x,b.y)),h2u(__floats2half2_rn(b.z,b.w)));
    *(uint4*)(dst+i)=r;
}

// ---------------- fp16 mma GEMM, up to 3 passes, split-K W pipelining ----------------
#define GW 32768
#define G_BYTES 196608
__global__ void __launch_bounds__(256,1) gemm_h(
        const __half* __restrict__ A1, const __half* __restrict__ W1, const float* __restrict__ b1, float s1, __half* __restrict__ o1,
        const __half* __restrict__ A2, const __half* __restrict__ W2, const float* __restrict__ b2, __half* __restrict__ o2,
        const __half* __restrict__ W3, const float* __restrict__ b3, __half* __restrict__ o3,
        const float* __restrict__ res, float* __restrict__ out32){
    extern __shared__ __half sh[];
    const uint32_t smb = smem_u32(sh);
    int tid=threadIdx.x, lane=tid&31, wid=tid>>5;
    int g=lane>>2, tig=lane&3, p=wid>>1, h=wid&1;
    int m0 = blockIdx.x*128;
    const int ria=(lane&7)+(lane&8), hi=(lane>>4)&1, sel=(lane>>3)&1, r7=lane&7, nsel=lane>>4;

    auto stageA = [&](const __half* A){
        #pragma unroll
        for(int i=0;i<16;i++){ int c=tid+i*256, r=c>>5, ch=c&31;
            CPAH(r*256 + ((ch^(r&7))<<3), A + (size_t)(m0+r)*256 + ch*8); }
    };
    auto stageWh = [&](const __half* W, int half, int slot){
        #pragma unroll
        for(int i=0;i<16;i++){ int c=tid+i*256, kr=c>>5, ch=c&31;
            CPAH(GW + slot*32768 + kr*256 + ((ch^(kr&7))<<3),
                 W + (size_t)(half*128+kr)*256 + ch*8); }
    };

    float acc[2][16][4];
    int row0 = p*32 + ria, row1 = row0 + 16;
    uint32_t a0b = smb + (uint32_t)row0*512, a1b = smb + (uint32_t)row1*512;
    int x0 = row0&7;

    auto compute_half = [&](int kh){
        #pragma unroll
        for(int kl=0;kl<8;kl++){
            int ki = kh*8 + kl;
            uint32_t qa0,qa1,qa2,qa3, ra0,ra1,ra2,ra3;
            LDSM4(qa0,qa1,qa2,qa3, a0b + (uint32_t)(((2*ki+hi)^x0)<<4));
            LDSM4(ra0,ra1,ra2,ra3, a1b + (uint32_t)(((2*ki+hi)^x0)<<4));
            int lrow = kl*16 + sel*8 + r7;
            uint32_t wr = smb + (uint32_t)(GW + kh*32768)*2 + (uint32_t)lrow*512; int xw=lrow&7;
            #pragma unroll
            for(int j=0;j<8;j++){
                int nt = h*16 + 2*j + nsel;
                uint32_t b0,b1,b2,b3;
                LDSM4T(b0,b1,b2,b3, wr + (uint32_t)((nt^xw)<<4));
                MMAH(acc[0][2*j],   qa0,qa1,qa2,qa3, b0,b1);
                MMAH(acc[0][2*j+1], qa0,qa1,qa2,qa3, b2,b3);
                MMAH(acc[1][2*j],   ra0,ra1,ra2,ra3, b0,b1);
                MMAH(acc[1][2*j+1], ra0,ra1,ra2,ra3, b2,b3);
            }
        }
    };
    auto epilogue = [&](const float* bias, float osc, __half* o16){
        #pragma unroll
        for(int rt=0;rt<2;rt++){
            int rr = m0 + p*32 + rt*16 + g;
            #pragma unroll
            for(int n=0;n<16;n++){
                int col = h*128 + n*8 + 2*tig;
                float2 bb = *(const float2*)&bias[col];
                float v0=acc[rt][n][0]+bb.x, v1=acc[rt][n][1]+bb.y;
                float v2=acc[rt][n][2]+bb.x, v3=acc[rt][n][3]+bb.y;
                if(out32){
                    float2 y0=*(const float2*)&res[(size_t)rr*256+col];
                    float2 y1=*(const float2*)&res[(size_t)(rr+8)*256+col];
                    float2 w0={v0+y0.x,v1+y0.y}, w1={v2+y1.x,v3+y1.y};
                    *(float2*)&out32[(size_t)rr*256+col]=w0;
                    *(float2*)&out32[(size_t)(rr+8)*256+col]=w1;
                } else {
                    *(__half2*)(o16+(size_t)rr*256+col)     = __floats2half2_rn(v0*osc,v1*osc);
                    *(__half2*)(o16+(size_t)(rr+8)*256+col) = __floats2half2_rn(v2*osc,v3*osc);
                }
            }
        }
    };
    auto zacc = [&](){
        #pragma unroll
        for(int rt=0;rt<2;rt++) for(int n=0;n<16;n++){ acc[rt][n][0]=0.f;acc[rt][n][1]=0.f;acc[rt][n][2]=0.f;acc[rt][n][3]=0.f; }
    };

    stageA(A1); stageWh(W1,0,0); CPC(); CPW0(); __syncthreads();
    stageWh(W1,1,1); CPC();
    zacc(); compute_half(0);
    CPW0(); __syncthreads();
    compute_half(1);
    epilogue(b1, s1, o1);
    if(W2){
        __syncthreads();
        stageA(A2); stageWh(W2,0,0); CPC(); CPW0(); __syncthreads();
        stageWh(W2,1,1); CPC();
        zacc(); compute_half(0);
        CPW0(); __syncthreads();
        if(W3){ stageWh(W3,0,0); CPC(); }
        compute_half(1);
        epilogue(b2, 1.f, o2);
        if(W3){
            CPW0(); __syncthreads();
            stageWh(W3,1,1); CPC();
            zacc(); compute_half(0);
            CPW0(); __syncthreads();
            compute_half(1);
            epilogue(b3, 1.f, o3);
        }
    }
}

// ---------------- flash attention: Bq=128, Bk=64, Q-in-regs, per-group interleave ----
// smem halfs: Q@0 (32768); K@32768 (2x16384); V@65536 (2x16384). 196608 B.
#define FK 32768
#define FV 65536
#define FL_BYTES 196608
__global__ void __launch_bounds__(256,1) flash_h(const __half* __restrict__ q,
        const __half* __restrict__ k, const __half* __restrict__ v, __half* __restrict__ o){
    extern __shared__ __half sh[];
    const uint32_t smb = smem_u32(sh);
    int tid=threadIdx.x, lane=tid&31, wid=tid>>5;
    int g=lane>>2, tig=lane&3;
    int b=blockIdx.y, qb=blockIdx.x;
    const __half* qg = q + ((size_t)b*SS + (size_t)qb*128)*CC;
    const __half* kg = k + (size_t)b*SS*CC;
    const __half* vg = v + (size_t)b*SS*CC;

    #pragma unroll
    for(int i=0;i<16;i++){ int c=tid+i*256, r=c>>5, ch=c&31;
        CPAH(r*256 + ((ch^(r&7))<<3), qg + (size_t)c*8); }
    #pragma unroll
    for(int i=0;i<8;i++){ int c=tid+i*256, r=c>>5, ch=c&31;
        int sw = r*256 + ((ch^(r&7))<<3);
        CPAH(FK + sw, kg + (size_t)c*8);
        CPAH(FV + sw, vg + (size_t)c*8); }
    CPC(); CPW0(); __syncthreads();

    const int hi=(lane>>4)&1, sel=(lane>>3)&1, r7=lane&7, nsel=lane>>4;
    const int rq = wid*16 + (lane&7) + (lane&8); const int rq7 = rq&7;
    const uint32_t aqb = smb + (uint32_t)rq*512;
    const int kkey = (lane&7) + ((lane>>4)<<3);
    const int kcs  = (lane>>3)&1;

    // Q resident in registers (loop-invariant)
    uint32_t qf[16][4];
    #pragma unroll
    for(int ki=0;ki<16;ki++)
        LDSM4(qf[ki][0],qf[ki][1],qf[ki][2],qf[ki][3], aqb + (uint32_t)(((2*ki+hi)^rq7)<<4));

    float acc[32][4];
    #pragma unroll
    for(int i=0;i<32;i++){ acc[i][0]=0.f;acc[i][1]=0.f;acc[i][2]=0.f;acc[i][3]=0.f; }
    float l0=0.f, l1=0.f;

    int buf=0;
    for(int t=0;t<64;t++){
        if(t>0){ CPW0(); }
        __syncthreads();
        if(t<63){
            const __half* kt = kg + (size_t)(t+1)*16384;
            const __half* vt = vg + (size_t)(t+1)*16384;
            int bo = (buf^1)*16384;
            #pragma unroll
            for(int i=0;i<8;i++){ int c=tid+i*256, r=c>>5, ch=c&31;
                int sw = r*256 + ((ch^(r&7))<<3);
                CPAH(FK + bo + sw, kt + (size_t)c*8);
                CPAH(FV + bo + sw, vt + (size_t)c*8); }
            CPC();
        }
        uint32_t kbb = smb + (uint32_t)(FK + buf*16384)*2;
        uint32_t vbb = smb + (uint32_t)(FV + buf*16384)*2;
        // per-group: QK(G) -> exp(G) -> PV(G); PV(G) overlaps QK(G+1) naturally
        #pragma unroll
        for(int G=0;G<4;G++){
            float s0[4]={0.f,0.f,0.f,0.f}, s1[4]={0.f,0.f,0.f,0.f};
            int krow = G*16 + kkey;
            uint32_t kr = kbb + (uint32_t)krow*512; int xk=krow&7;
            #pragma unroll
            for(int ki=0;ki<16;ki++){
                uint32_t b0,b1,b2,b3;
                LDSM4(b0,b1,b2,b3, kr + (uint32_t)(((2*ki+kcs)^xk)<<4));
                MMAH(s0, qf[ki][0],qf[ki][1],qf[ki][2],qf[ki][3], b0,b1);
                MMAH(s1, qf[ki][0],qf[ki][1],qf[ki][2],qf[ki][3], b2,b3);
            }
            uint32_t pa0,pa1,pa2,pa3;
            {
                uint32_t e0,e1;
                __half2 h0 = __floats2half2_rn(s0[0], s0[1]);
                __half2 h1 = __floats2half2_rn(s0[2], s0[3]);
                asm("ex2.approx.f16x2 %0, %1;":"=r"(e0):"r"(h2u(h0)));
                asm("ex2.approx.f16x2 %0, %1;":"=r"(e1):"r"(h2u(h1)));
                pa0=e0; pa1=e1;
                float2 f0=__half22float2(*(__half2*)&e0), f1=__half22float2(*(__half2*)&e1);
                l0 += f0.x+f0.y; l1 += f1.x+f1.y;
                h0 = __floats2half2_rn(s1[0], s1[1]);
                h1 = __floats2half2_rn(s1[2], s1[3]);
                asm("ex2.approx.f16x2 %0, %1;":"=r"(e0):"r"(h2u(h0)));
                asm("ex2.approx.f16x2 %0, %1;":"=r"(e1):"r"(h2u(h1)));
                pa2=e0; pa3=e1;
                f0=__half22float2(*(__half2*)&e0); f1=__half22float2(*(__half2*)&e1);
                l0 += f0.x+f0.y; l1 += f1.x+f1.y;
            }
            int vrow = G*16 + sel*8 + r7;
            uint32_t vr = vbb + (uint32_t)vrow*512; int xv=vrow&7;
            #pragma unroll
            for(int j=0;j<16;j++){
                int nt = 2*j + nsel;
                uint32_t b0,b1,b2,b3;
                LDSM4T(b0,b1,b2,b3, vr + (uint32_t)((nt^xv)<<4));
                MMAH(acc[2*j],   pa0,pa1,pa2,pa3, b0,b1);
                MMAH(acc[2*j+1], pa0,pa1,pa2,pa3, b2,b3);
            }
        }
        buf ^= 1;
    }
    l0 += __shfl_xor_sync(~0u,l0,1); l0 += __shfl_xor_sync(~0u,l0,2);
    l1 += __shfl_xor_sync(~0u,l1,1); l1 += __shfl_xor_sync(~0u,l1,2);
    float inv0 = 1.f/l0, inv1 = 1.f/l1;
    __half* o0 = o + ((size_t)b*SS + (size_t)qb*128 + wid*16 + g)*CC;
    __half* o1 = o0 + 8*CC;
    #pragma unroll
    for(int n=0;n<32;n++){
        int col = n*8 + 2*tig;
        *(__half2*)(o0+col) = __floats2half2_rn(acc[n][0]*inv0, acc[n][1]*inv0);
        *(__half2*)(o1+col) = __floats2half2_rn(acc[n][2]*inv1, acc[n][3]*inv1);
    }
}

// ---------------- launcher ----------------
extern "C" void kernel_launch(void* const* d_in, const int* in_sizes, int n_in,
                              void* d_out, int out_size){
    const float* inputs  = (const float*)d_in[0];
    const float* context = (const float*)d_in[1];
    const float* Wq=(const float*)d_in[2];  const float* bq=(const float*)d_in[3];
    const float* Wk=(const float*)d_in[4];  const float* bk=(const float*)d_in[5];
    const float* Wv=(const float*)d_in[6];  const float* bv=(const float*)d_in[7];
    const float* Wp=(const float*)d_in[8];  const float* bp=(const float*)d_in[9];
    const float* gamma=(const float*)d_in[10]; const float* beta=(const float*)d_in[11];
    float* out=(float*)d_out;
    float *xn; __half *xn16,*ct16,*q16,*k16,*v16,*o16,*wq16,*wk16,*wv16,*wp16;
    cudaGetSymbolAddress((void**)&xn,g_xn);
    cudaGetSymbolAddress((void**)&xn16,g_xn16); cudaGetSymbolAddress((void**)&ct16,g_ct16);
    cudaGetSymbolAddress((void**)&q16,g_q16);   cudaGetSymbolAddress((void**)&k16,g_k16);
    cudaGetSymbolAddress((void**)&v16,g_v16);   cudaGetSymbolAddress((void**)&o16,g_o16);
    cudaGetSymbolAddress((void**)&wq16,g_wq16); cudaGetSymbolAddress((void**)&wk16,g_wk16);
    cudaGetSymbolAddress((void**)&wv16,g_wv16); cudaGetSymbolAddress((void**)&wp16,g_wp16);
    cudaFuncSetAttribute(flash_h, cudaFuncAttributeMaxDynamicSharedMemorySize, FL_BYTES);
    cudaFuncSetAttribute(gemm_h,  cudaFuncAttributeMaxDynamicSharedMemorySize, G_BYTES);

    const float QSC = 0.09016994f;   // log2(e)/16
    ln_kernel<<<M_TOT/8,256>>>(inputs,gamma,beta,xn,xn16);
    cvt_all<<<2176,256>>>(context, ct16, Wq,Wk,Wv,Wp, wq16,wk16,wv16,wp16);
    gemm_h<<<M_TOT/128,256,G_BYTES>>>(xn16, wq16,bq,QSC,q16,
                                      ct16, wk16,bk,k16,
                                      wv16,bv,v16, nullptr,nullptr);
    flash_h<<<dim3(SS/128, BN), 256, FL_BYTES>>>(q16,k16,v16,o16);
    gemm_h<<<M_TOT/128,256,G_BYTES>>>(o16, wp16,bp,1.f,nullptr,
                                      nullptr, nullptr,nullptr,nullptr,
                                      nullptr,nullptr,nullptr, xn, out);
}

// round 14
// speedup vs baseline: 1.1768x; 1.1768x over previous
#include <cuda_runtime.h>
#include <cuda_fp16.h>
#include <math.h>
#include <stdint.h>

#define BN 4
#define SS 4096
#define CC 256
#define M_TOT (BN*SS)

__device__ float  g_xn  [(size_t)BN*SS*CC];
__device__ __half g_xn16[(size_t)BN*SS*CC];
__device__ __half g_ct16[(size_t)BN*SS*CC];
__device__ __half g_q16 [(size_t)BN*SS*CC];
__device__ __half g_k16 [(size_t)BN*SS*CC];
__device__ __half g_v16 [(size_t)BN*SS*CC];
__device__ __half g_o16 [(size_t)BN*SS*CC];
__device__ __half g_wq16[CC*CC];
__device__ __half g_wk16[CC*CC];
__device__ __half g_wv16[CC*CC];
__device__ __half g_wp16[CC*CC];

__device__ __forceinline__ uint32_t smem_u32(const void* p){
    uint32_t a; asm("{ .reg .u64 t; cvta.to.shared.u64 t, %1; cvt.u32.u64 %0, t; }":"=r"(a):"l"(p)); return a;
}
#define MMAH(d,a0,a1,a2,a3,b0,b1) \
    asm("mma.sync.aligned.m16n8k16.row.col.f32.f16.f16.f32 {%0,%1,%2,%3},{%4,%5,%6,%7},{%8,%9},{%0,%1,%2,%3};" \
        :"+f"(d[0]),"+f"(d[1]),"+f"(d[2]),"+f"(d[3]) \
        :"r"(a0),"r"(a1),"r"(a2),"r"(a3),"r"(b0),"r"(b1))
#define LDSM4(r0,r1,r2,r3,a) asm volatile("ldmatrix.sync.aligned.m8n8.x4.shared.b16 {%0,%1,%2,%3},[%4];" \
        :"=r"(r0),"=r"(r1),"=r"(r2),"=r"(r3):"r"(a))
#define LDSM4T(r0,r1,r2,r3,a) asm volatile("ldmatrix.sync.aligned.m8n8.x4.trans.shared.b16 {%0,%1,%2,%3},[%4];" \
        :"=r"(r0),"=r"(r1),"=r"(r2),"=r"(r3):"r"(a))
#define CPAH(off_h, src) asm volatile("cp.async.cg.shared.global [%0], [%1], 16;"::"r"(smb+(uint32_t)((off_h)*2)),"l"(src):"memory")
#define CPC()  asm volatile("cp.async.commit_group;":::"memory")
#define CPW0() asm volatile("cp.async.wait_group 0;":::"memory")
__device__ __forceinline__ uint32_t h2u(__half2 x){ return *(uint32_t*)&x; }

// ---------------- fused prep: LayerNorm + fp32->fp16 converts ----------------
__global__ void prep_kernel(const float* __restrict__ x, const float* __restrict__ gamma,
        const float* __restrict__ beta, float* __restrict__ out32, __half* __restrict__ out16,
        const float* __restrict__ ctx, __half* __restrict__ dctx,
        const float* __restrict__ Wq, const float* __restrict__ Wk,
        const float* __restrict__ Wv, const float* __restrict__ Wp,
        __half* __restrict__ dwq, __half* __restrict__ dwk,
        __half* __restrict__ dwv, __half* __restrict__ dwp){
    int blk = blockIdx.x;
    if(blk < 2048){
        int wid = threadIdx.x>>5, lane = threadIdx.x&31;
        size_t row = (size_t)blk*8 + wid;
        const float* xr = x + row*CC + lane*8;
        float4 v0 = *(const float4*)xr, v1 = *(const float4*)(xr+4);
        float s = v0.x+v0.y+v0.z+v0.w+v1.x+v1.y+v1.z+v1.w;
        #pragma unroll
        for(int o=16;o;o>>=1) s += __shfl_xor_sync(~0u,s,o);
        float mu = s*(1.f/CC);
        v0.x-=mu;v0.y-=mu;v0.z-=mu;v0.w-=mu;v1.x-=mu;v1.y-=mu;v1.z-=mu;v1.w-=mu;
        float q = v0.x*v0.x+v0.y*v0.y+v0.z*v0.z+v0.w*v0.w+v1.x*v1.x+v1.y*v1.y+v1.z*v1.z+v1.w*v1.w;
        #pragma unroll
        for(int o=16;o;o>>=1) q += __shfl_xor_sync(~0u,q,o);
        float rs = rsqrtf(q*(1.f/CC)+1e-3f);
        const float4 ga0 = *(const float4*)(gamma+lane*8), ga1 = *(const float4*)(gamma+lane*8+4);
        const float4 be0 = *(const float4*)(beta +lane*8), be1 = *(const float4*)(beta +lane*8+4);
        float4 o0,o1;
        o0.x=v0.x*rs*ga0.x+be0.x; o0.y=v0.y*rs*ga0.y+be0.y; o0.z=v0.z*rs*ga0.z+be0.z; o0.w=v0.w*rs*ga0.w+be0.w;
        o1.x=v1.x*rs*ga1.x+be1.x; o1.y=v1.y*rs*ga1.y+be1.y; o1.z=v1.z*rs*ga1.z+be1.z; o1.w=v1.w*rs*ga1.w+be1.w;
        float* op = out32 + row*CC + lane*8;
        *(float4*)op = o0; *(float4*)(op+4) = o1;
        uint4 hp = make_uint4(h2u(__floats2half2_rn(o0.x,o0.y)), h2u(__floats2half2_rn(o0.z,o0.w)),
                              h2u(__floats2half2_rn(o1.x,o1.y)), h2u(__floats2half2_rn(o1.z,o1.w)));
        *(uint4*)(out16 + row*CC + lane*8) = hp;
        return;
    }
    const float* src; __half* dst; size_t base;
    if(blk < 4096){ src=ctx; dst=dctx; base=(size_t)(blk-2048)*2048; }
    else{
        int w=(blk-4096)>>5, off=(blk-4096)&31;
        src = w==0?Wq : w==1?Wk : w==2?Wv : Wp;
        dst = w==0?dwq: w==1?dwk: w==2?dwv: dwp;
        base = (size_t)off*2048;
    }
    size_t i = base + (size_t)threadIdx.x*8;
    float4 a=*(const float4*)(src+i), b=*(const float4*)(src+i+4);
    uint4 r = make_uint4(h2u(__floats2half2_rn(a.x,a.y)),h2u(__floats2half2_rn(a.z,a.w)),
                         h2u(__floats2half2_rn(b.x,b.y)),h2u(__floats2half2_rn(b.z,b.w)));
    *(uint4*)(dst+i)=r;
}

// ---------------- fp16 mma GEMM, up to 3 passes, split-K W pipelining ----------------
#define GW 32768
#define G_BYTES 196608
__global__ void __launch_bounds__(256,1) gemm_h(
        const __half* __restrict__ A1, const __half* __restrict__ W1, const float* __restrict__ b1, float s1, __half* __restrict__ o1,
        const __half* __restrict__ A2, const __half* __restrict__ W2, const float* __restrict__ b2, __half* __restrict__ o2,
        const __half* __restrict__ W3, const float* __restrict__ b3, __half* __restrict__ o3,
        const float* __restrict__ res, float* __restrict__ out32){
    extern __shared__ __half sh[];
    const uint32_t smb = smem_u32(sh);
    int tid=threadIdx.x, lane=tid&31, wid=tid>>5;
    int g=lane>>2, tig=lane&3, p=wid>>1, h=wid&1;
    int m0 = blockIdx.x*128;
    const int ria=(lane&7)+(lane&8), hi=(lane>>4)&1, sel=(lane>>3)&1, r7=lane&7, nsel=lane>>4;

    auto stageA = [&](const __half* A){
        #pragma unroll
        for(int i=0;i<16;i++){ int c=tid+i*256, r=c>>5, ch=c&31;
            CPAH(r*256 + ((ch^(r&7))<<3), A + (size_t)(m0+r)*256 + ch*8); }
    };
    auto stageWh = [&](const __half* W, int half, int slot){
        #pragma unroll
        for(int i=0;i<16;i++){ int c=tid+i*256, kr=c>>5, ch=c&31;
            CPAH(GW + slot*32768 + kr*256 + ((ch^(kr&7))<<3),
                 W + (size_t)(half*128+kr)*256 + ch*8); }
    };

    float acc[2][16][4];
    int row0 = p*32 + ria, row1 = row0 + 16;
    uint32_t a0b = smb + (uint32_t)row0*512, a1b = smb + (uint32_t)row1*512;
    int x0 = row0&7;

    auto compute_half = [&](int kh){
        #pragma unroll
        for(int kl=0;kl<8;kl++){
            int ki = kh*8 + kl;
            uint32_t qa0,qa1,qa2,qa3, ra0,ra1,ra2,ra3;
            LDSM4(qa0,qa1,qa2,qa3, a0b + (uint32_t)(((2*ki+hi)^x0)<<4));
            LDSM4(ra0,ra1,ra2,ra3, a1b + (uint32_t)(((2*ki+hi)^x0)<<4));
            int lrow = kl*16 + sel*8 + r7;
            uint32_t wr = smb + (uint32_t)(GW + kh*32768)*2 + (uint32_t)lrow*512; int xw=lrow&7;
            #pragma unroll
            for(int j=0;j<8;j++){
                int nt = h*16 + 2*j + nsel;
                uint32_t b0,b1,b2,b3;
                LDSM4T(b0,b1,b2,b3, wr + (uint32_t)((nt^xw)<<4));
                MMAH(acc[0][2*j],   qa0,qa1,qa2,qa3, b0,b1);
                MMAH(acc[0][2*j+1], qa0,qa1,qa2,qa3, b2,b3);
                MMAH(acc[1][2*j],   ra0,ra1,ra2,ra3, b0,b1);
                MMAH(acc[1][2*j+1], ra0,ra1,ra2,ra3, b2,b3);
            }
        }
    };
    auto epilogue = [&](const float* bias, float osc, __half* o16){
        #pragma unroll
        for(int rt=0;rt<2;rt++){
            int rr = m0 + p*32 + rt*16 + g;
            #pragma unroll
            for(int n=0;n<16;n++){
                int col = h*128 + n*8 + 2*tig;
                float2 bb = *(const float2*)&bias[col];
                float v0=acc[rt][n][0]+bb.x, v1=acc[rt][n][1]+bb.y;
                float v2=acc[rt][n][2]+bb.x, v3=acc[rt][n][3]+bb.y;
                if(out32){
                    float2 y0=*(const float2*)&res[(size_t)rr*256+col];
                    float2 y1=*(const float2*)&res[(size_t)(rr+8)*256+col];
                    float2 w0={v0+y0.x,v1+y0.y}, w1={v2+y1.x,v3+y1.y};
                    *(float2*)&out32[(size_t)rr*256+col]=w0;
                    *(float2*)&out32[(size_t)(rr+8)*256+col]=w1;
                } else {
                    *(__half2*)(o16+(size_t)rr*256+col)     = __floats2half2_rn(v0*osc,v1*osc);
                    *(__half2*)(o16+(size_t)(rr+8)*256+col) = __floats2half2_rn(v2*osc,v3*osc);
                }
            }
        }
    };
    auto zacc = [&](){
        #pragma unroll
        for(int rt=0;rt<2;rt++) for(int n=0;n<16;n++){ acc[rt][n][0]=0.f;acc[rt][n][1]=0.f;acc[rt][n][2]=0.f;acc[rt][n][3]=0.f; }
    };

    stageA(A1); stageWh(W1,0,0); CPC(); CPW0(); __syncthreads();
    stageWh(W1,1,1); CPC();
    zacc(); compute_half(0);
    CPW0(); __syncthreads();
    compute_half(1);
    epilogue(b1, s1, o1);
    if(W2){
        __syncthreads();
        stageA(A2); stageWh(W2,0,0); CPC(); CPW0(); __syncthreads();
        stageWh(W2,1,1); CPC();
        zacc(); compute_half(0);
        CPW0(); __syncthreads();
        if(W3){ stageWh(W3,0,0); CPC(); }
        compute_half(1);
        epilogue(b2, 1.f, o2);
        if(W3){
            CPW0(); __syncthreads();
            stageWh(W3,1,1); CPC();
            zacc(); compute_half(0);
            CPW0(); __syncthreads();
            compute_half(1);
            epilogue(b3, 1.f, o3);
        }
    }
}

// ---------------- flash: Bq=128, Bk=64, 4 row-groups x 2 key-halves, P via smem ----
// smem halfs: Q@0 (32768); K@32768 (2x16384); V@65536 (2x16384);
//             P@98304 (128 rows x pitch72 = 9216, single buffer); l @107520 (256 floats)
#define FK 32768
#define FV 65536
#define FP 98304
#define FLL 107520
#define FL_BYTES 216064
__global__ void __launch_bounds__(256,1) flash_h(const __half* __restrict__ q,
        const __half* __restrict__ k, const __half* __restrict__ v, __half* __restrict__ o){
    extern __shared__ __half sh[];
    const uint32_t smb = smem_u32(sh);
    int tid=threadIdx.x, lane=tid&31, wid=tid>>5;
    int g=lane>>2, tig=lane&3;
    int rg=wid>>1, h=wid&1;
    int b=blockIdx.y, qb=blockIdx.x;
    const __half* qg = q + ((size_t)b*SS + (size_t)qb*128)*CC;
    const __half* kg = k + (size_t)b*SS*CC;
    const __half* vg = v + (size_t)b*SS*CC;

    #pragma unroll
    for(int i=0;i<16;i++){ int c=tid+i*256, r=c>>5, ch=c&31;
        CPAH(r*256 + ((ch^(r&7))<<3), qg + (size_t)c*8); }
    #pragma unroll
    for(int i=0;i<8;i++){ int c=tid+i*256, r=c>>5, ch=c&31;
        int sw = r*256 + ((ch^(r&7))<<3);
        CPAH(FK + sw, kg + (size_t)c*8);
        CPAH(FV + sw, vg + (size_t)c*8); }
    CPC();

    const int sel=(lane>>3)&1, r7=lane&7, nsel=lane>>4, hi=(lane>>4)&1;
    const int ria=(lane&7)+(lane&8);
    const int kkey=(lane&7)+((lane>>4)<<3), kcs=(lane>>3)&1;
    const uint32_t aq0 = smb + (uint32_t)(rg*32+ria)*512;
    const uint32_t aq1 = aq0 + 16*512;
    const int xq = (rg*32+ria)&7;
    const uint32_t prd_row = (uint32_t)(rg*32 + (lane&15))*144 + (uint32_t)((lane>>4)*8)*2;
    const int prow0 = rg*32 + g;

    float acc[2][16][4];
    #pragma unroll
    for(int rt=0;rt<2;rt++) for(int n=0;n<16;n++){ acc[rt][n][0]=0.f;acc[rt][n][1]=0.f;acc[rt][n][2]=0.f;acc[rt][n][3]=0.f; }
    float lr[2][2]={{0.f,0.f},{0.f,0.f}};

    __half* pwb = sh + FP;
    uint32_t pbb = smb + (uint32_t)FP*2;

    int buf=0;
    for(int t=0;t<64;t++){
        CPW0();
        __syncthreads();      // tile data ready; prior PV reads of P and V done
        if(t<63){
            const __half* kt = kg + (size_t)(t+1)*16384;
            const __half* vt = vg + (size_t)(t+1)*16384;
            int bo = (buf^1)*16384;
            #pragma unroll
            for(int i=0;i<8;i++){ int c=tid+i*256, r=c>>5, ch=c&31;
                int sw = r*256 + ((ch^(r&7))<<3);
                CPAH(FK + bo + sw, kt + (size_t)c*8);
                CPAH(FV + bo + sw, vt + (size_t)c*8); }
            CPC();
        }
        uint32_t kbb = smb + (uint32_t)(FK + buf*16384)*2;
        uint32_t vbb = smb + (uint32_t)(FV + buf*16384)*2;

        // ---- QK: this warp's 32 rows x its 32 keys ----
        float s[2][2][2][4];
        #pragma unroll
        for(int rt=0;rt<2;rt++) for(int G=0;G<2;G++) for(int pp=0;pp<2;pp++)
            { s[rt][G][pp][0]=0.f; s[rt][G][pp][1]=0.f; s[rt][G][pp][2]=0.f; s[rt][G][pp][3]=0.f; }
        #pragma unroll
        for(int ki=0;ki<16;ki++){
            uint32_t qa0,qa1,qa2,qa3, ra0,ra1,ra2,ra3;
            LDSM4(qa0,qa1,qa2,qa3, aq0 + (uint32_t)(((2*ki+hi)^xq)<<4));
            LDSM4(ra0,ra1,ra2,ra3, aq1 + (uint32_t)(((2*ki+hi)^xq)<<4));
            #pragma unroll
            for(int G=0;G<2;G++){
                int krow = h*32 + G*16 + kkey;
                uint32_t b0,b1,b2,b3;
                LDSM4(b0,b1,b2,b3, kbb + (uint32_t)krow*512 + (uint32_t)(((2*ki+kcs)^(krow&7))<<4));
                MMAH(s[0][G][0], qa0,qa1,qa2,qa3, b0,b1);
                MMAH(s[0][G][1], qa0,qa1,qa2,qa3, b2,b3);
                MMAH(s[1][G][0], ra0,ra1,ra2,ra3, b0,b1);
                MMAH(s[1][G][1], ra0,ra1,ra2,ra3, b2,b3);
            }
        }
        // ---- exp + publish P ----
        #pragma unroll
        for(int rt=0;rt<2;rt++){
            #pragma unroll
            for(int G=0;G<2;G++){
                #pragma unroll
                for(int pp=0;pp<2;pp++){
                    float* sv = s[rt][G][pp];
                    uint32_t e0,e1;
                    __half2 h0 = __floats2half2_rn(sv[0], sv[1]);
                    __half2 h1 = __floats2half2_rn(sv[2], sv[3]);
                    asm("ex2.approx.f16x2 %0, %1;":"=r"(e0):"r"(h2u(h0)));
                    asm("ex2.approx.f16x2 %0, %1;":"=r"(e1):"r"(h2u(h1)));
                    float2 f0=__half22float2(*(__half2*)&e0), f1=__half22float2(*(__half2*)&e1);
                    lr[rt][0] += f0.x+f0.y; lr[rt][1] += f1.x+f1.y;
                    int nb = h*32 + G*16 + pp*8 + 2*tig;
                    int rw = prow0 + rt*16;
                    *(uint32_t*)(pwb + rw*72 + nb)     = e0;
                    *(uint32_t*)(pwb + (rw+8)*72 + nb) = e1;
                }
            }
        }
        __syncthreads();   // P published
        // ---- PV: this warp's 32 rows x its 128 channels, all 64 keys ----
        #pragma unroll
        for(int kp=0;kp<4;kp++){
            uint32_t pa0[4], pa1[4];
            uint32_t pr = pbb + prd_row + (uint32_t)(kp*16)*2;
            LDSM4(pa0[0],pa0[1],pa0[2],pa0[3], pr);
            LDSM4(pa1[0],pa1[1],pa1[2],pa1[3], pr + 16*144);
            int vrow = kp*16 + sel*8 + r7; int xv = vrow&7;
            uint32_t vr = vbb + (uint32_t)vrow*512;
            #pragma unroll
            for(int j=0;j<8;j++){
                int ntg = h*16 + 2*j + nsel;
                uint32_t b0,b1,b2,b3;
                LDSM4T(b0,b1,b2,b3, vr + (uint32_t)((ntg^xv)<<4));
                MMAH(acc[0][2*j],   pa0[0],pa0[1],pa0[2],pa0[3], b0,b1);
                MMAH(acc[0][2*j+1], pa0[0],pa0[1],pa0[2],pa0[3], b2,b3);
                MMAH(acc[1][2*j],   pa1[0],pa1[1],pa1[2],pa1[3], b0,b1);
                MMAH(acc[1][2*j+1], pa1[0],pa1[1],pa1[2],pa1[3], b2,b3);
            }
        }
        buf ^= 1;
    }
    // combine l across tig, then across key-halves via smem
    #pragma unroll
    for(int rt=0;rt<2;rt++){
        #pragma unroll
        for(int rh=0;rh<2;rh++){
            lr[rt][rh] += __shfl_xor_sync(~0u,lr[rt][rh],1);
            lr[rt][rh] += __shfl_xor_sync(~0u,lr[rt][rh],2);
        }
    }
    float* lsm = (float*)(sh + FLL);
    if(tig==0){
        #pragma unroll
        for(int rt=0;rt<2;rt++){
            int r0 = rg*32 + rt*16 + g;
            lsm[r0*2+h]     = lr[rt][0];
            lsm[(r0+8)*2+h] = lr[rt][1];
        }
    }
    __syncthreads();
    #pragma unroll
    for(int rt=0;rt<2;rt++){
        int r0 = rg*32 + rt*16 + g;
        float inv0 = 1.f/(lsm[r0*2] + lsm[r0*2+1]);
        float inv1 = 1.f/(lsm[(r0+8)*2] + lsm[(r0+8)*2+1]);
        __half* o0 = o + ((size_t)b*SS + (size_t)qb*128 + r0)*CC;
        __half* o1 = o0 + 8*CC;
        #pragma unroll
        for(int n=0;n<16;n++){
            int col = h*128 + n*8 + 2*tig;
            *(__half2*)(o0+col) = __floats2half2_rn(acc[rt][n][0]*inv0, acc[rt][n][1]*inv0);
            *(__half2*)(o1+col) = __floats2half2_rn(acc[rt][n][2]*inv1, acc[rt][n][3]*inv1);
        }
    }
}

// ---------------- launcher ----------------
extern "C" void kernel_launch(void* const* d_in, const int* in_sizes, int n_in,
                              void* d_out, int out_size){
    const float* inputs  = (const float*)d_in[0];
    const float* context = (const float*)d_in[1];
    const float* Wq=(const float*)d_in[2];  const float* bq=(const float*)d_in[3];
    const float* Wk=(const float*)d_in[4];  const float* bk=(const float*)d_in[5];
    const float* Wv=(const float*)d_in[6];  const float* bv=(const float*)d_in[7];
    const float* Wp=(const float*)d_in[8];  const float* bp=(const float*)d_in[9];
    const float* gamma=(const float*)d_in[10]; const float* beta=(const float*)d_in[11];
    float* out=(float*)d_out;
    float *xn; __half *xn16,*ct16,*q16,*k16,*v16,*o16,*wq16,*wk16,*wv16,*wp16;
    cudaGetSymbolAddress((void**)&xn,g_xn);
    cudaGetSymbolAddress((void**)&xn16,g_xn16); cudaGetSymbolAddress((void**)&ct16,g_ct16);
    cudaGetSymbolAddress((void**)&q16,g_q16);   cudaGetSymbolAddress((void**)&k16,g_k16);
    cudaGetSymbolAddress((void**)&v16,g_v16);   cudaGetSymbolAddress((void**)&o16,g_o16);
    cudaGetSymbolAddress((void**)&wq16,g_wq16); cudaGetSymbolAddress((void**)&wk16,g_wk16);
    cudaGetSymbolAddress((void**)&wv16,g_wv16); cudaGetSymbolAddress((void**)&wp16,g_wp16);
    cudaFuncSetAttribute(flash_h, cudaFuncAttributeMaxDynamicSharedMemorySize, FL_BYTES);
    cudaFuncSetAttribute(gemm_h,  cudaFuncAttributeMaxDynamicSharedMemorySize, G_BYTES);

    const float QSC = 0.09016994f;   // log2(e)/16
    prep_kernel<<<4224,256>>>(inputs,gamma,beta,xn,xn16,
                              context,ct16, Wq,Wk,Wv,Wp, wq16,wk16,wv16,wp16);
    gemm_h<<<M_TOT/128,256,G_BYTES>>>(xn16, wq16,bq,QSC,q16,
                                      ct16, wk16,bk,k16,
                                      wv16,bv,v16, nullptr,nullptr);
    flash_h<<<dim3(SS/128, BN), 256, FL_BYTES>>>(q16,k16,v16,o16);
    gemm_h<<<M_TOT/128,256,G_BYTES>>>(o16, wp16,bp,1.f,nullptr,
                                      nullptr, nullptr,nullptr,nullptr,
                                      nullptr,nullptr,nullptr, xn, out);
}

// round 15
// speedup vs baseline: 1.1837x; 1.0059x over previous
#include <cuda_runtime.h>
#include <cuda_fp16.h>
#include <math.h>
#include <stdint.h>

#define BN 4
#define SS 4096
#define CC 256
#define M_TOT (BN*SS)

__device__ float  g_xn  [(size_t)BN*SS*CC];
__device__ __half g_xn16[(size_t)BN*SS*CC];
__device__ __half g_ct16[(size_t)BN*SS*CC];
__device__ __half g_q16 [(size_t)BN*SS*CC];
__device__ __half g_k16 [(size_t)BN*SS*CC];
__device__ __half g_v16 [(size_t)BN*SS*CC];
__device__ __half g_o16 [(size_t)BN*SS*CC];
__device__ __half g_wq16[CC*CC];
__device__ __half g_wk16[CC*CC];
__device__ __half g_wv16[CC*CC];
__device__ __half g_wp16[CC*CC];

__device__ __forceinline__ uint32_t smem_u32(const void* p){
    uint32_t a; asm("{ .reg .u64 t; cvta.to.shared.u64 t, %1; cvt.u32.u64 %0, t; }":"=r"(a):"l"(p)); return a;
}
#define MMAH(d,a0,a1,a2,a3,b0,b1) \
    asm("mma.sync.aligned.m16n8k16.row.col.f32.f16.f16.f32 {%0,%1,%2,%3},{%4,%5,%6,%7},{%8,%9},{%0,%1,%2,%3};" \
        :"+f"(d[0]),"+f"(d[1]),"+f"(d[2]),"+f"(d[3]) \
        :"r"(a0),"r"(a1),"r"(a2),"r"(a3),"r"(b0),"r"(b1))
#define LDSM4(r0,r1,r2,r3,a) asm volatile("ldmatrix.sync.aligned.m8n8.x4.shared.b16 {%0,%1,%2,%3},[%4];" \
        :"=r"(r0),"=r"(r1),"=r"(r2),"=r"(r3):"r"(a))
#define LDSM4T(r0,r1,r2,r3,a) asm volatile("ldmatrix.sync.aligned.m8n8.x4.trans.shared.b16 {%0,%1,%2,%3},[%4];" \
        :"=r"(r0),"=r"(r1),"=r"(r2),"=r"(r3):"r"(a))
#define CPAH(off_h, src) asm volatile("cp.async.cg.shared.global [%0], [%1], 16;"::"r"(smb+(uint32_t)((off_h)*2)),"l"(src):"memory")
#define CPC()  asm volatile("cp.async.commit_group;":::"memory")
#define CPW0() asm volatile("cp.async.wait_group 0;":::"memory")
__device__ __forceinline__ uint32_t h2u(__half2 x){ return *(uint32_t*)&x; }

// ---------------- fused prep: LayerNorm + fp32->fp16 converts ----------------
__global__ void prep_kernel(const float* __restrict__ x, const float* __restrict__ gamma,
        const float* __restrict__ beta, float* __restrict__ out32, __half* __restrict__ out16,
        const float* __restrict__ ctx, __half* __restrict__ dctx,
        const float* __restrict__ Wq, const float* __restrict__ Wk,
        const float* __restrict__ Wv, const float* __restrict__ Wp,
        __half* __restrict__ dwq, __half* __restrict__ dwk,
        __half* __restrict__ dwv, __half* __restrict__ dwp){
    int blk = blockIdx.x;
    if(blk < 2048){
        int wid = threadIdx.x>>5, lane = threadIdx.x&31;
        size_t row = (size_t)blk*8 + wid;
        const float* xr = x + row*CC + lane*8;
        float4 v0 = *(const float4*)xr, v1 = *(const float4*)(xr+4);
        float s = v0.x+v0.y+v0.z+v0.w+v1.x+v1.y+v1.z+v1.w;
        #pragma unroll
        for(int o=16;o;o>>=1) s += __shfl_xor_sync(~0u,s,o);
        float mu = s*(1.f/CC);
        v0.x-=mu;v0.y-=mu;v0.z-=mu;v0.w-=mu;v1.x-=mu;v1.y-=mu;v1.z-=mu;v1.w-=mu;
        float q = v0.x*v0.x+v0.y*v0.y+v0.z*v0.z+v0.w*v0.w+v1.x*v1.x+v1.y*v1.y+v1.z*v1.z+v1.w*v1.w;
        #pragma unroll
        for(int o=16;o;o>>=1) q += __shfl_xor_sync(~0u,q,o);
        float rs = rsqrtf(q*(1.f/CC)+1e-3f);
        const float4 ga0 = *(const float4*)(gamma+lane*8), ga1 = *(const float4*)(gamma+lane*8+4);
        const float4 be0 = *(const float4*)(beta +lane*8), be1 = *(const float4*)(beta +lane*8+4);
        float4 o0,o1;
        o0.x=v0.x*rs*ga0.x+be0.x; o0.y=v0.y*rs*ga0.y+be0.y; o0.z=v0.z*rs*ga0.z+be0.z; o0.w=v0.w*rs*ga0.w+be0.w;
        o1.x=v1.x*rs*ga1.x+be1.x; o1.y=v1.y*rs*ga1.y+be1.y; o1.z=v1.z*rs*ga1.z+be1.z; o1.w=v1.w*rs*ga1.w+be1.w;
        float* op = out32 + row*CC + lane*8;
        *(float4*)op = o0; *(float4*)(op+4) = o1;
        uint4 hp = make_uint4(h2u(__floats2half2_rn(o0.x,o0.y)), h2u(__floats2half2_rn(o0.z,o0.w)),
                              h2u(__floats2half2_rn(o1.x,o1.y)), h2u(__floats2half2_rn(o1.z,o1.w)));
        *(uint4*)(out16 + row*CC + lane*8) = hp;
        return;
    }
    const float* src; __half* dst; size_t base;
    if(blk < 4096){ src=ctx; dst=dctx; base=(size_t)(blk-2048)*2048; }
    else{
        int w=(blk-4096)>>5, off=(blk-4096)&31;
        src = w==0?Wq : w==1?Wk : w==2?Wv : Wp;
        dst = w==0?dwq: w==1?dwk: w==2?dwv: dwp;
        base = (size_t)off*2048;
    }
    size_t i = base + (size_t)threadIdx.x*8;
    float4 a=*(const float4*)(src+i), b=*(const float4*)(src+i+4);
    uint4 r = make_uint4(h2u(__floats2half2_rn(a.x,a.y)),h2u(__floats2half2_rn(a.z,a.w)),
                         h2u(__floats2half2_rn(b.x,b.y)),h2u(__floats2half2_rn(b.z,b.w)));
    *(uint4*)(dst+i)=r;
}

// ---------------- single-pass fp16 mma GEMM body (macro-shared) ----------------
#define GW 32768
#define G_BYTES 196608

// QKV: grid (128 m-tiles, 3 outputs); each CTA one pass, fp16 out
__global__ void __launch_bounds__(256,1) gemm_qkv(
        const __half* __restrict__ xn16, const __half* __restrict__ ct16,
        const __half* __restrict__ wq, const __half* __restrict__ wk, const __half* __restrict__ wv,
        const float* __restrict__ bq, const float* __restrict__ bk, const float* __restrict__ bv,
        __half* __restrict__ q16, __half* __restrict__ k16, __half* __restrict__ v16,
        float qsc){
    extern __shared__ __half sh[];
    const uint32_t smb = smem_u32(sh);
    int tid=threadIdx.x, lane=tid&31, wid=tid>>5;
    int g=lane>>2, tig=lane&3, p=wid>>1, h=wid&1;
    int m0 = blockIdx.x*128;
    int y  = blockIdx.y;
    const __half* A   = (y==0)? xn16 : ct16;
    const __half* W   = (y==0)? wq : (y==1)? wk : wv;
    const float*  bias= (y==0)? bq : (y==1)? bk : bv;
    __half*       o16 = (y==0)? q16 : (y==1)? k16 : v16;
    float osc = (y==0)? qsc : 1.f;
    const int ria=(lane&7)+(lane&8), hi=(lane>>4)&1, sel=(lane>>3)&1, r7=lane&7, nsel=lane>>4;

    // stage A + W half0
    #pragma unroll
    for(int i=0;i<16;i++){ int c=tid+i*256, r=c>>5, ch=c&31;
        CPAH(r*256 + ((ch^(r&7))<<3), A + (size_t)(m0+r)*256 + ch*8); }
    #pragma unroll
    for(int i=0;i<16;i++){ int c=tid+i*256, kr=c>>5, ch=c&31;
        CPAH(GW + kr*256 + ((ch^(kr&7))<<3), W + (size_t)kr*256 + ch*8); }
    CPC(); CPW0(); __syncthreads();
    // stage W half1
    #pragma unroll
    for(int i=0;i<16;i++){ int c=tid+i*256, kr=c>>5, ch=c&31;
        CPAH(GW + 32768 + kr*256 + ((ch^(kr&7))<<3), W + (size_t)(128+kr)*256 + ch*8); }
    CPC();

    float acc[2][16][4];
    #pragma unroll
    for(int rt=0;rt<2;rt++) for(int n=0;n<16;n++){ acc[rt][n][0]=0.f;acc[rt][n][1]=0.f;acc[rt][n][2]=0.f;acc[rt][n][3]=0.f; }
    int row0 = p*32 + ria, row1 = row0 + 16;
    uint32_t a0b = smb + (uint32_t)row0*512, a1b = smb + (uint32_t)row1*512;
    int x0 = row0&7;

    #pragma unroll
    for(int kh=0;kh<2;kh++){
        if(kh==1){ CPW0(); __syncthreads(); }
        #pragma unroll
        for(int kl=0;kl<8;kl++){
            int ki = kh*8 + kl;
            uint32_t qa0,qa1,qa2,qa3, ra0,ra1,ra2,ra3;
            LDSM4(qa0,qa1,qa2,qa3, a0b + (uint32_t)(((2*ki+hi)^x0)<<4));
            LDSM4(ra0,ra1,ra2,ra3, a1b + (uint32_t)(((2*ki+hi)^x0)<<4));
            int lrow = kl*16 + sel*8 + r7;
            uint32_t wr = smb + (uint32_t)(GW + kh*32768)*2 + (uint32_t)lrow*512; int xw=lrow&7;
            #pragma unroll
            for(int j=0;j<8;j++){
                int nt = h*16 + 2*j + nsel;
                uint32_t b0,b1,b2,b3;
                LDSM4T(b0,b1,b2,b3, wr + (uint32_t)((nt^xw)<<4));
                MMAH(acc[0][2*j],   qa0,qa1,qa2,qa3, b0,b1);
                MMAH(acc[0][2*j+1], qa0,qa1,qa2,qa3, b2,b3);
                MMAH(acc[1][2*j],   ra0,ra1,ra2,ra3, b0,b1);
                MMAH(acc[1][2*j+1], ra0,ra1,ra2,ra3, b2,b3);
            }
        }
    }
    #pragma unroll
    for(int rt=0;rt<2;rt++){
        int rr = m0 + p*32 + rt*16 + g;
        #pragma unroll
        for(int n=0;n<16;n++){
            int col = h*128 + n*8 + 2*tig;
            float2 bb = *(const float2*)&bias[col];
            float v0=(acc[rt][n][0]+bb.x)*osc, v1=(acc[rt][n][1]+bb.y)*osc;
            float v2=(acc[rt][n][2]+bb.x)*osc, v3=(acc[rt][n][3]+bb.y)*osc;
            *(__half2*)(o16+(size_t)rr*256+col)     = __floats2half2_rn(v0,v1);
            *(__half2*)(o16+(size_t)(rr+8)*256+col) = __floats2half2_rn(v2,v3);
        }
    }
}

// final: out = o16@Wp + bp + xn  (fp32 out)
__global__ void __launch_bounds__(256,1) gemm_out(
        const __half* __restrict__ A, const __half* __restrict__ W,
        const float* __restrict__ bias, const float* __restrict__ res,
        float* __restrict__ out32){
    extern __shared__ __half sh[];
    const uint32_t smb = smem_u32(sh);
    int tid=threadIdx.x, lane=tid&31, wid=tid>>5;
    int g=lane>>2, tig=lane&3, p=wid>>1, h=wid&1;
    int m0 = blockIdx.x*128;
    const int ria=(lane&7)+(lane&8), hi=(lane>>4)&1, sel=(lane>>3)&1, r7=lane&7, nsel=lane>>4;

    #pragma unroll
    for(int i=0;i<16;i++){ int c=tid+i*256, r=c>>5, ch=c&31;
        CPAH(r*256 + ((ch^(r&7))<<3), A + (size_t)(m0+r)*256 + ch*8); }
    #pragma unroll
    for(int i=0;i<16;i++){ int c=tid+i*256, kr=c>>5, ch=c&31;
        CPAH(GW + kr*256 + ((ch^(kr&7))<<3), W + (size_t)kr*256 + ch*8); }
    CPC(); CPW0(); __syncthreads();
    #pragma unroll
    for(int i=0;i<16;i++){ int c=tid+i*256, kr=c>>5, ch=c&31;
        CPAH(GW + 32768 + kr*256 + ((ch^(kr&7))<<3), W + (size_t)(128+kr)*256 + ch*8); }
    CPC();

    float acc[2][16][4];
    #pragma unroll
    for(int rt=0;rt<2;rt++) for(int n=0;n<16;n++){ acc[rt][n][0]=0.f;acc[rt][n][1]=0.f;acc[rt][n][2]=0.f;acc[rt][n][3]=0.f; }
    int row0 = p*32 + ria, row1 = row0 + 16;
    uint32_t a0b = smb + (uint32_t)row0*512, a1b = smb + (uint32_t)row1*512;
    int x0 = row0&7;

    #pragma unroll
    for(int kh=0;kh<2;kh++){
        if(kh==1){ CPW0(); __syncthreads(); }
        #pragma unroll
        for(int kl=0;kl<8;kl++){
            int ki = kh*8 + kl;
            uint32_t qa0,qa1,qa2,qa3, ra0,ra1,ra2,ra3;
            LDSM4(qa0,qa1,qa2,qa3, a0b + (uint32_t)(((2*ki+hi)^x0)<<4));
            LDSM4(ra0,ra1,ra2,ra3, a1b + (uint32_t)(((2*ki+hi)^x0)<<4));
            int lrow = kl*16 + sel*8 + r7;
            uint32_t wr = smb + (uint32_t)(GW + kh*32768)*2 + (uint32_t)lrow*512; int xw=lrow&7;
            #pragma unroll
            for(int j=0;j<8;j++){
                int nt = h*16 + 2*j + nsel;
                uint32_t b0,b1,b2,b3;
                LDSM4T(b0,b1,b2,b3, wr + (uint32_t)((nt^xw)<<4));
                MMAH(acc[0][2*j],   qa0,qa1,qa2,qa3, b0,b1);
                MMAH(acc[0][2*j+1], qa0,qa1,qa2,qa3, b2,b3);
                MMAH(acc[1][2*j],   ra0,ra1,ra2,ra3, b0,b1);
                MMAH(acc[1][2*j+1], ra0,ra1,ra2,ra3, b2,b3);
            }
        }
    }
    #pragma unroll
    for(int rt=0;rt<2;rt++){
        int rr = m0 + p*32 + rt*16 + g;
        #pragma unroll
        for(int n=0;n<16;n++){
            int col = h*128 + n*8 + 2*tig;
            float2 bb = *(const float2*)&bias[col];
            float2 y0=*(const float2*)&res[(size_t)rr*256+col];
            float2 y1=*(const float2*)&res[(size_t)(rr+8)*256+col];
            float2 w0={acc[rt][n][0]+bb.x+y0.x, acc[rt][n][1]+bb.y+y0.y};
            float2 w1={acc[rt][n][2]+bb.x+y1.x, acc[rt][n][3]+bb.y+y1.y};
            *(float2*)&out32[(size_t)rr*256+col]=w0;
            *(float2*)&out32[(size_t)(rr+8)*256+col]=w1;
        }
    }
}

// ---------------- flash: Bq=128, Bk=64, 4 row-groups x 2 key-halves, P via smem ----
#define FK 32768
#define FV 65536
#define FP 98304
#define FLL 107520
#define FL_BYTES 216064
__global__ void __launch_bounds__(256,1) flash_h(const __half* __restrict__ q,
        const __half* __restrict__ k, const __half* __restrict__ v, __half* __restrict__ o){
    extern __shared__ __half sh[];
    const uint32_t smb = smem_u32(sh);
    int tid=threadIdx.x, lane=tid&31, wid=tid>>5;
    int g=lane>>2, tig=lane&3;
    int rg=wid>>1, h=wid&1;
    int b=blockIdx.y, qb=blockIdx.x;
    const __half* qg = q + ((size_t)b*SS + (size_t)qb*128)*CC;
    const __half* kg = k + (size_t)b*SS*CC;
    const __half* vg = v + (size_t)b*SS*CC;

    #pragma unroll
    for(int i=0;i<16;i++){ int c=tid+i*256, r=c>>5, ch=c&31;
        CPAH(r*256 + ((ch^(r&7))<<3), qg + (size_t)c*8); }
    #pragma unroll
    for(int i=0;i<8;i++){ int c=tid+i*256, r=c>>5, ch=c&31;
        int sw = r*256 + ((ch^(r&7))<<3);
        CPAH(FK + sw, kg + (size_t)c*8);
        CPAH(FV + sw, vg + (size_t)c*8); }
    CPC();

    const int sel=(lane>>3)&1, r7=lane&7, nsel=lane>>4, hi=(lane>>4)&1;
    const int ria=(lane&7)+(lane&8);
    const int kkey=(lane&7)+((lane>>4)<<3), kcs=(lane>>3)&1;
    const uint32_t aq0 = smb + (uint32_t)(rg*32+ria)*512;
    const uint32_t aq1 = aq0 + 16*512;
    const int xq = (rg*32+ria)&7;
    const uint32_t prd_row = (uint32_t)(rg*32 + (lane&15))*144 + (uint32_t)((lane>>4)*8)*2;
    const int prow0 = rg*32 + g;

    float acc[2][16][4];
    #pragma unroll
    for(int rt=0;rt<2;rt++) for(int n=0;n<16;n++){ acc[rt][n][0]=0.f;acc[rt][n][1]=0.f;acc[rt][n][2]=0.f;acc[rt][n][3]=0.f; }
    float lr[2][2]={{0.f,0.f},{0.f,0.f}};

    __half* pwb = sh + FP;
    uint32_t pbb = smb + (uint32_t)FP*2;

    int buf=0;
    for(int t=0;t<64;t++){
        CPW0();
        __syncthreads();
        if(t<63){
            const __half* kt = kg + (size_t)(t+1)*16384;
            const __half* vt = vg + (size_t)(t+1)*16384;
            int bo = (buf^1)*16384;
            #pragma unroll
            for(int i=0;i<8;i++){ int c=tid+i*256, r=c>>5, ch=c&31;
                int sw = r*256 + ((ch^(r&7))<<3);
                CPAH(FK + bo + sw, kt + (size_t)c*8);
                CPAH(FV + bo + sw, vt + (size_t)c*8); }
            CPC();
        }
        uint32_t kbb = smb + (uint32_t)(FK + buf*16384)*2;
        uint32_t vbb = smb + (uint32_t)(FV + buf*16384)*2;

        float s[2][2][2][4];
        #pragma unroll
        for(int rt=0;rt<2;rt++) for(int G=0;G<2;G++) for(int pp=0;pp<2;pp++)
            { s[rt][G][pp][0]=0.f; s[rt][G][pp][1]=0.f; s[rt][G][pp][2]=0.f; s[rt][G][pp][3]=0.f; }
        #pragma unroll
        for(int ki=0;ki<16;ki++){
            uint32_t qa0,qa1,qa2,qa3, ra0,ra1,ra2,ra3;
            LDSM4(qa0,qa1,qa2,qa3, aq0 + (uint32_t)(((2*ki+hi)^xq)<<4));
            LDSM4(ra0,ra1,ra2,ra3, aq1 + (uint32_t)(((2*ki+hi)^xq)<<4));
            #pragma unroll
            for(int G=0;G<2;G++){
                int krow = h*32 + G*16 + kkey;
                uint32_t b0,b1,b2,b3;
                LDSM4(b0,b1,b2,b3, kbb + (uint32_t)krow*512 + (uint32_t)(((2*ki+kcs)^(krow&7))<<4));
                MMAH(s[0][G][0], qa0,qa1,qa2,qa3, b0,b1);
                MMAH(s[0][G][1], qa0,qa1,qa2,qa3, b2,b3);
                MMAH(s[1][G][0], ra0,ra1,ra2,ra3, b0,b1);
                MMAH(s[1][G][1], ra0,ra1,ra2,ra3, b2,b3);
            }
        }
        #pragma unroll
        for(int rt=0;rt<2;rt++){
            #pragma unroll
            for(int G=0;G<2;G++){
                #pragma unroll
                for(int pp=0;pp<2;pp++){
                    float* sv = s[rt][G][pp];
                    uint32_t e0,e1;
                    __half2 h0 = __floats2half2_rn(sv[0], sv[1]);
                    __half2 h1 = __floats2half2_rn(sv[2], sv[3]);
                    asm("ex2.approx.f16x2 %0, %1;":"=r"(e0):"r"(h2u(h0)));
                    asm("ex2.approx.f16x2 %0, %1;":"=r"(e1):"r"(h2u(h1)));
                    float2 f0=__half22float2(*(__half2*)&e0), f1=__half22float2(*(__half2*)&e1);
                    lr[rt][0] += f0.x+f0.y; lr[rt][1] += f1.x+f1.y;
                    int nb = h*32 + G*16 + pp*8 + 2*tig;
                    int rw = prow0 + rt*16;
                    *(uint32_t*)(pwb + rw*72 + nb)     = e0;
                    *(uint32_t*)(pwb + (rw+8)*72 + nb) = e1;
                }
            }
        }
        __syncthreads();
        #pragma unroll
        for(int kp=0;kp<4;kp++){
            uint32_t pa0[4], pa1[4];
            uint32_t pr = pbb + prd_row + (uint32_t)(kp*16)*2;
            LDSM4(pa0[0],pa0[1],pa0[2],pa0[3], pr);
            LDSM4(pa1[0],pa1[1],pa1[2],pa1[3], pr + 16*144);
            int vrow = kp*16 + sel*8 + r7; int xv = vrow&7;
            uint32_t vr = vbb + (uint32_t)vrow*512;
            #pragma unroll
            for(int j=0;j<8;j++){
                int ntg = h*16 + 2*j + nsel;
                uint32_t b0,b1,b2,b3;
                LDSM4T(b0,b1,b2,b3, vr + (uint32_t)((ntg^xv)<<4));
                MMAH(acc[0][2*j],   pa0[0],pa0[1],pa0[2],pa0[3], b0,b1);
                MMAH(acc[0][2*j+1], pa0[0],pa0[1],pa0[2],pa0[3], b2,b3);
                MMAH(acc[1][2*j],   pa1[0],pa1[1],pa1[2],pa1[3], b0,b1);
                MMAH(acc[1][2*j+1], pa1[0],pa1[1],pa1[2],pa1[3], b2,b3);
            }
        }
        buf ^= 1;
    }
    #pragma unroll
    for(int rt=0;rt<2;rt++){
        #pragma unroll
        for(int rh=0;rh<2;rh++){
            lr[rt][rh] += __shfl_xor_sync(~0u,lr[rt][rh],1);
            lr[rt][rh] += __shfl_xor_sync(~0u,lr[rt][rh],2);
        }
    }
    float* lsm = (float*)(sh + FLL);
    if(tig==0){
        #pragma unroll
        for(int rt=0;rt<2;rt++){
            int r0 = rg*32 + rt*16 + g;
            lsm[r0*2+h]     = lr[rt][0];
            lsm[(r0+8)*2+h] = lr[rt][1];
        }
    }
    __syncthreads();
    #pragma unroll
    for(int rt=0;rt<2;rt++){
        int r0 = rg*32 + rt*16 + g;
        float inv0 = 1.f/(lsm[r0*2] + lsm[r0*2+1]);
        float inv1 = 1.f/(lsm[(r0+8)*2] + lsm[(r0+8)*2+1]);
        __half* o0 = o + ((size_t)b*SS + (size_t)qb*128 + r0)*CC;
        __half* o1 = o0 + 8*CC;
        #pragma unroll
        for(int n=0;n<16;n++){
            int col = h*128 + n*8 + 2*tig;
            *(__half2*)(o0+col) = __floats2half2_rn(acc[rt][n][0]*inv0, acc[rt][n][1]*inv0);
            *(__half2*)(o1+col) = __floats2half2_rn(acc[rt][n][2]*inv1, acc[rt][n][3]*inv1);
        }
    }
}

// ---------------- launcher ----------------
extern "C" void kernel_launch(void* const* d_in, const int* in_sizes, int n_in,
                              void* d_out, int out_size){
    const float* inputs  = (const float*)d_in[0];
    const float* context = (const float*)d_in[1];
    const float* Wq=(const float*)d_in[2];  const float* bq=(const float*)d_in[3];
    const float* Wk=(const float*)d_in[4];  const float* bk=(const float*)d_in[5];
    const float* Wv=(const float*)d_in[6];  const float* bv=(const float*)d_in[7];
    const float* Wp=(const float*)d_in[8];  const float* bp=(const float*)d_in[9];
    const float* gamma=(const float*)d_in[10]; const float* beta=(const float*)d_in[11];
    float* out=(float*)d_out;
    float *xn; __half *xn16,*ct16,*q16,*k16,*v16,*o16,*wq16,*wk16,*wv16,*wp16;
    cudaGetSymbolAddress((void**)&xn,g_xn);
    cudaGetSymbolAddress((void**)&xn16,g_xn16); cudaGetSymbolAddress((void**)&ct16,g_ct16);
    cudaGetSymbolAddress((void**)&q16,g_q16);   cudaGetSymbolAddress((void**)&k16,g_k16);
    cudaGetSymbolAddress((void**)&v16,g_v16);   cudaGetSymbolAddress((void**)&o16,g_o16);
    cudaGetSymbolAddress((void**)&wq16,g_wq16); cudaGetSymbolAddress((void**)&wk16,g_wk16);
    cudaGetSymbolAddress((void**)&wv16,g_wv16); cudaGetSymbolAddress((void**)&wp16,g_wp16);
    cudaFuncSetAttribute(flash_h,  cudaFuncAttributeMaxDynamicSharedMemorySize, FL_BYTES);
    cudaFuncSetAttribute(gemm_qkv, cudaFuncAttributeMaxDynamicSharedMemorySize, G_BYTES);
    cudaFuncSetAttribute(gemm_out, cudaFuncAttributeMaxDynamicSharedMemorySize, G_BYTES);

    const float QSC = 0.09016994f;   // log2(e)/16
    prep_kernel<<<4224,256>>>(inputs,gamma,beta,xn,xn16,
                              context,ct16, Wq,Wk,Wv,Wp, wq16,wk16,wv16,wp16);
    gemm_qkv<<<dim3(M_TOT/128,3),256,G_BYTES>>>(xn16,ct16, wq16,wk16,wv16,
                                                bq,bk,bv, q16,k16,v16, QSC);
    flash_h<<<dim3(SS/128, BN), 256, FL_BYTES>>>(q16,k16,v16,o16);
    gemm_out<<<M_TOT/128,256,G_BYTES>>>(o16, wp16, bp, xn, out);
}